// round 1
// baseline (speedup 1.0000x reference)
#include <cuda_runtime.h>
#include <cuda_bf16.h>
#include <cstdint>

// Problem constants
#define RANK 2
#define INPUT_SIZE 8
#define HIDDEN 1024
#define NMIX 4
#define ALPHA 0.1f
#define BASE_SCALE 500.0f
#define DDIM 12              // 2*RANK + INPUT_SIZE
#define BATCH 64
#define SEQ 512
#define SPAN_D 10            // RANK + INPUT_SIZE

// ---------------- scratch (device globals: allocation-free) ----------------
__device__ float2 g_n2[HIDDEN];            // (n0, n1) per hidden unit
__device__ float2 g_mA[HIDDEN];            // alpha*s*(m0, m1)
__device__ float  g_IA[HIDDEN * 8];        // alpha*I  [h][8]
__device__ float  g_pinvT[HIDDEN * SPAN_D];// pinv transposed: [h][d]
__device__ float  g_hid[(size_t)BATCH * SEQ * HIDDEN]; // 128 MB hiddens

// ============================ setup kernel ============================
__global__ void __launch_bounds__(1024) setup_kernel(
    const float* __restrict__ eps,     // (4,1024,12)
    const float* __restrict__ means,   // (4,12)
    const float* __restrict__ stril,   // (4,12,12)
    const float* __restrict__ mw)      // (4,)
{
    __shared__ float  sL[NMIX][DDIM][DDIM];
    __shared__ float  sM[NMIX][DDIM];
    __shared__ float  sw[NMIX];
    __shared__ double sGw[32][100];    // per-warp partial Gram
    __shared__ double sG[100];
    __shared__ double sGinv[100];

    const int tid  = threadIdx.x;
    const int lane = tid & 31;
    const int wid  = tid >> 5;

    // L = tril(raw,-1) + (|diag-1e-12|+1e-12) * I
    if (tid < NMIX * DDIM * DDIM) {
        int k = tid / (DDIM * DDIM);
        int r = (tid / DDIM) % DDIM;
        int c = tid % DDIM;
        float raw = stril[tid];
        float v;
        if (r > c)      v = raw;
        else if (r == c) v = fabsf(raw - 1e-12f) + 1e-12f;
        else            v = 0.f;
        sL[k][r][c] = v;
    }
    if (tid < NMIX * DDIM) sM[tid / DDIM][tid % DDIM] = means[tid];
    if (tid == 0) {
        float t4[NMIX]; float s = 0.f;
        #pragma unroll
        for (int k = 0; k < NMIX; k++) { t4[k] = fmaxf(mw[k], 1e-6f); s += t4[k]; }
        #pragma unroll
        for (int k = 0; k < NMIX; k++) sw[k] = t4[k] / s;
    }
    __syncthreads();

    // mixed[h][e] = sum_k w_k * (means[k][e] + sum_d eps[k,h,d]*L[k,e,d])
    const int h = tid;
    float mix[DDIM];
    #pragma unroll
    for (int e = 0; e < DDIM; e++) mix[e] = 0.f;

    #pragma unroll
    for (int k = 0; k < NMIX; k++) {
        float wk = sw[k];
        const float4* p = (const float4*)(eps + ((size_t)k * HIDDEN + h) * DDIM);
        float4 a = p[0], b = p[1], c = p[2];
        float ep[DDIM] = {a.x,a.y,a.z,a.w, b.x,b.y,b.z,b.w, c.x,c.y,c.z,c.w};
        #pragma unroll
        for (int e = 0; e < DDIM; e++) {
            float s = sM[k][e];
            #pragma unroll
            for (int d = 0; d < DDIM; d++) {   // L upper part is 0
                s = fmaf(ep[d], sL[k][e][d], s);
            }
            mix[e] = fmaf(wk, s, mix[e]);
        }
    }

    // derive per-h constants
    const float AS = ALPHA * (BASE_SCALE / (float)HIDDEN);
    float span[SPAN_D];
    span[0] = mix[0]; span[1] = mix[1];
    #pragma unroll
    for (int d = 0; d < 8; d++) span[2 + d] = mix[4 + d];

    g_n2[h] = make_float2(mix[2], mix[3]);
    g_mA[h] = make_float2(AS * mix[0], AS * mix[1]);
    #pragma unroll
    for (int d = 0; d < 8; d++) g_IA[h * 8 + d] = ALPHA * mix[4 + d];

    // Gram G = span^T span (fp64), block reduction
    #pragma unroll 1
    for (int p = 0; p < 100; p++) {
        int a = p / 10, b = p % 10;
        double v = (double)span[a] * (double)span[b];
        #pragma unroll
        for (int o = 16; o > 0; o >>= 1) v += __shfl_xor_sync(0xffffffffu, v, o);
        if (lane == 0) sGw[wid][p] = v;
    }
    __syncthreads();
    if (tid < 100) {
        double s = 0.0;
        #pragma unroll 1
        for (int w = 0; w < 32; w++) s += sGw[w][tid];
        sG[tid] = s;
    }
    __syncthreads();

    // invert G (SPD -> Gauss-Jordan, no pivoting), fp64, single thread
    if (tid == 0) {
        double A[10][10], B[10][10];
        for (int i = 0; i < 10; i++)
            for (int j = 0; j < 10; j++) {
                A[i][j] = sG[i * 10 + j];
                B[i][j] = (i == j) ? 1.0 : 0.0;
            }
        for (int k = 0; k < 10; k++) {
            double d = 1.0 / A[k][k];
            for (int j = 0; j < 10; j++) { A[k][j] *= d; B[k][j] *= d; }
            for (int i = 0; i < 10; i++) {
                if (i == k) continue;
                double f = A[i][k];
                for (int j = 0; j < 10; j++) {
                    A[i][j] -= f * A[k][j];
                    B[i][j] -= f * B[k][j];
                }
            }
        }
        for (int i = 0; i < 100; i++) sGinv[i] = B[i / 10][i % 10];
    }
    __syncthreads();

    // pinv[d][h] = sum_j Ginv[d][j] * span[h][j]  (store transposed [h][d])
    #pragma unroll
    for (int d = 0; d < SPAN_D; d++) {
        double s = 0.0;
        #pragma unroll
        for (int j = 0; j < SPAN_D; j++) s += sGinv[d * 10 + j] * (double)span[j];
        g_pinvT[h * SPAN_D + d] = (float)s;
    }
}

// ============================ RNN kernel ============================
// One CTA per batch, one thread per hidden unit. h lives in a register.
__global__ void __launch_bounds__(1024, 1) rnn_kernel(const float* __restrict__ x)
{
    __shared__ float sx[SEQ * INPUT_SIZE];     // 16 KB: x[b] staged
    __shared__ float sred[2][2][32];           // ping-pong reduction buffers

    const int tid  = threadIdx.x;
    const int lane = tid & 31;
    const int wid  = tid >> 5;
    const int b    = blockIdx.x;

    // stage x[b] into smem (coalesced float4)
    ((float4*)sx)[tid] = ((const float4*)(x + (size_t)b * SEQ * INPUT_SIZE))[tid];

    const float2 nv = g_n2[tid];
    const float2 mA = g_mA[tid];
    const float4 iaA = ((const float4*)g_IA)[tid * 2 + 0];
    const float4 iaB = ((const float4*)g_IA)[tid * 2 + 1];

    float h = 0.f;
    float* hout = g_hid + ((size_t)b << 19) + tid;   // [b][t][h], 512*1024 = 1<<19
    __syncthreads();

    int par = 0;
    #pragma unroll 1
    for (int t = 0; t < SEQ; t++) {
        // tanh(h) = 1 - 2/(exp(2h)+1)  (MUFU.EX2 + MUFU.RCP, ~1e-6 accurate)
        float e  = __expf(2.f * h);
        float th = 1.f - __fdividef(2.f, e + 1.f);

        float p0 = th * nv.x, p1 = th * nv.y;
        #pragma unroll
        for (int o = 16; o > 0; o >>= 1) {
            p0 += __shfl_xor_sync(0xffffffffu, p0, o);
            p1 += __shfl_xor_sync(0xffffffffu, p1, o);
        }
        if (lane == 0) { sred[par][0][wid] = p0; sred[par][1][wid] = p1; }
        __syncthreads();
        // redundant stage-2 butterfly in every warp (no 2nd barrier, no broadcast)
        float q0 = sred[par][0][lane];
        float q1 = sred[par][1][lane];
        #pragma unroll
        for (int o = 16; o > 0; o >>= 1) {
            q0 += __shfl_xor_sync(0xffffffffu, q0, o);
            q1 += __shfl_xor_sync(0xffffffffu, q1, o);
        }

        // x_t @ (alpha*I)^T  (uniform smem broadcast loads)
        float4 xa = ((const float4*)sx)[t * 2 + 0];
        float4 xb = ((const float4*)sx)[t * 2 + 1];
        float xi = xa.x * iaA.x + xa.y * iaA.y + xa.z * iaA.z + xa.w * iaA.w
                 + xb.x * iaB.x + xb.y * iaB.y + xb.z * iaB.z + xb.w * iaB.w;

        // h_new = (1-a)h + a*s*(v0*m0 + v1*m1) + a*(x I^T)   (scales prefolded)
        h = 0.9f * h + q0 * mA.x + q1 * mA.y + xi;

        hout[(size_t)t << 10] = h;   // coalesced, off critical path
        par ^= 1;
    }
}

// ============================ projection kernel ============================
// out[b,t,d] = sum_h pinv[d][h] * hid[b,t,h]; thread per (b,t).
__global__ void __launch_bounds__(256) proj_kernel(float* __restrict__ out)
{
    extern __shared__ float spv[];   // [1024][12] padded pinv rows, 48 KB
    const int tid = threadIdx.x;
    for (int i = tid; i < HIDDEN * 12; i += 256) {
        int hh = i / 12, d = i % 12;
        spv[i] = (d < SPAN_D) ? g_pinvT[hh * SPAN_D + d] : 0.f;
    }
    __syncthreads();

    const int bt = blockIdx.x * 256 + tid;          // 0..32767
    const float4* hp = (const float4*)(g_hid + (size_t)bt * HIDDEN);

    float acc[SPAN_D];
    #pragma unroll
    for (int d = 0; d < SPAN_D; d++) acc[d] = 0.f;

    #pragma unroll 4
    for (int j = 0; j < HIDDEN / 4; j++) {
        float4 hv = hp[j];
        const float* base = &spv[(j * 4) * 12];
        {
            const float4* pv = (const float4*)(base + 0);
            float4 a = pv[0], bq = pv[1], c = pv[2];
            acc[0] += hv.x*a.x;  acc[1] += hv.x*a.y;  acc[2] += hv.x*a.z;  acc[3] += hv.x*a.w;
            acc[4] += hv.x*bq.x; acc[5] += hv.x*bq.y; acc[6] += hv.x*bq.z; acc[7] += hv.x*bq.w;
            acc[8] += hv.x*c.x;  acc[9] += hv.x*c.y;
        }
        {
            const float4* pv = (const float4*)(base + 12);
            float4 a = pv[0], bq = pv[1], c = pv[2];
            acc[0] += hv.y*a.x;  acc[1] += hv.y*a.y;  acc[2] += hv.y*a.z;  acc[3] += hv.y*a.w;
            acc[4] += hv.y*bq.x; acc[5] += hv.y*bq.y; acc[6] += hv.y*bq.z; acc[7] += hv.y*bq.w;
            acc[8] += hv.y*c.x;  acc[9] += hv.y*c.y;
        }
        {
            const float4* pv = (const float4*)(base + 24);
            float4 a = pv[0], bq = pv[1], c = pv[2];
            acc[0] += hv.z*a.x;  acc[1] += hv.z*a.y;  acc[2] += hv.z*a.z;  acc[3] += hv.z*a.w;
            acc[4] += hv.z*bq.x; acc[5] += hv.z*bq.y; acc[6] += hv.z*bq.z; acc[7] += hv.z*bq.w;
            acc[8] += hv.z*c.x;  acc[9] += hv.z*c.y;
        }
        {
            const float4* pv = (const float4*)(base + 36);
            float4 a = pv[0], bq = pv[1], c = pv[2];
            acc[0] += hv.w*a.x;  acc[1] += hv.w*a.y;  acc[2] += hv.w*a.z;  acc[3] += hv.w*a.w;
            acc[4] += hv.w*bq.x; acc[5] += hv.w*bq.y; acc[6] += hv.w*bq.z; acc[7] += hv.w*bq.w;
            acc[8] += hv.w*c.x;  acc[9] += hv.w*c.y;
        }
    }

    float* op = out + (size_t)bt * SPAN_D;
    #pragma unroll
    for (int d = 0; d < SPAN_D; d++) op[d] = acc[d];
}

// ============================ launcher ============================
extern "C" void kernel_launch(void* const* d_in, const int* in_sizes, int n_in,
                              void* d_out, int out_size)
{
    const float* x     = (const float*)d_in[0];   // (64,512,8)
    const float* eps   = (const float*)d_in[1];   // (4,1024,12)
    const float* means = (const float*)d_in[2];   // (4,12)
    const float* stril = (const float*)d_in[3];   // (4,12,12)
    const float* mw    = (const float*)d_in[4];   // (4,)
    float* out = (float*)d_out;                   // (64,512,10)

    static bool attr_set = false;
    if (!attr_set) {
        cudaFuncSetAttribute(proj_kernel,
                             cudaFuncAttributeMaxDynamicSharedMemorySize,
                             HIDDEN * 12 * sizeof(float));
        attr_set = true;
    }

    setup_kernel<<<1, 1024>>>(eps, means, stril, mw);
    rnn_kernel<<<BATCH, 1024>>>(x);
    proj_kernel<<<(BATCH * SEQ) / 256, 256, HIDDEN * 12 * sizeof(float)>>>(out);
}

// round 4
// speedup vs baseline: 2.1089x; 2.1089x over previous
#include <cuda_runtime.h>
#include <cuda_bf16.h>
#include <cstdint>

// Problem constants
#define RANK 2
#define INPUT_SIZE 8
#define HIDDEN 1024
#define NMIX 4
#define ALPHA 0.1f
#define BASE_SCALE 500.0f
#define DDIM 12              // 2*RANK + INPUT_SIZE
#define BATCH 64
#define SEQ 512
#define SPAN_D 10            // RANK + INPUT_SIZE

// ---------------- scratch (device globals: allocation-free) ----------------
__device__ float2 g_n2[HIDDEN];            // (n0, n1) per hidden unit
__device__ float2 g_mA[HIDDEN];            // alpha*s*(m0, m1)
__device__ float  g_IA[HIDDEN * 8];        // alpha*I  [h][8]
__device__ float  g_span[HIDDEN * SPAN_D]; // span matrix scratch [h][d]
__device__ float  g_pinvT[HIDDEN * SPAN_D];// pinv transposed: [h][d]
__device__ float  g_hid[(size_t)BATCH * SEQ * HIDDEN]; // 128 MB hiddens

// ============================ setup kernel ============================
__global__ void __launch_bounds__(1024) setup_kernel(
    const float* __restrict__ eps,     // (4,1024,12)
    const float* __restrict__ means,   // (4,12)
    const float* __restrict__ stril,   // (4,12,12)
    const float* __restrict__ mw)      // (4,)
{
    __shared__ float  sL[NMIX][DDIM][DDIM];
    __shared__ float  sM[NMIX][DDIM];
    __shared__ float  sw[NMIX];
    __shared__ double sPart[100][8];   // Gram partials: pair x segment
    __shared__ double sA[100];         // Gram / GJ workspace
    __shared__ double sB[100];         // GJ inverse accumulator
    __shared__ float  sGf[100];        // Ginv in fp32

    const int tid = threadIdx.x;

    // L = tril(raw,-1) + (|diag-1e-12|+1e-12) * I
    if (tid < NMIX * DDIM * DDIM) {
        int r = (tid / DDIM) % DDIM;
        int c = tid % DDIM;
        float raw = stril[tid];
        float v;
        if (r > c)      v = raw;
        else if (r == c) v = fabsf(raw - 1e-12f) + 1e-12f;
        else            v = 0.f;
        sL[tid / (DDIM * DDIM)][r][c] = v;
    }
    if (tid < NMIX * DDIM) sM[tid / DDIM][tid % DDIM] = means[tid];
    if (tid == 0) {
        float t4[NMIX]; float s = 0.f;
        #pragma unroll
        for (int k = 0; k < NMIX; k++) { t4[k] = fmaxf(mw[k], 1e-6f); s += t4[k]; }
        #pragma unroll
        for (int k = 0; k < NMIX; k++) sw[k] = t4[k] / s;
    }
    __syncthreads();

    // mixed[h][e] = sum_k w_k * (means[k][e] + sum_{d<=e} eps[k,h,d]*L[k,e,d])
    const int h = tid;
    float mix[DDIM];
    #pragma unroll
    for (int e = 0; e < DDIM; e++) mix[e] = 0.f;

    #pragma unroll
    for (int k = 0; k < NMIX; k++) {
        float wk = sw[k];
        const float4* p = (const float4*)(eps + ((size_t)k * HIDDEN + h) * DDIM);
        float4 a = p[0], b = p[1], c = p[2];
        float ep[DDIM] = {a.x,a.y,a.z,a.w, b.x,b.y,b.z,b.w, c.x,c.y,c.z,c.w};
        #pragma unroll
        for (int e = 0; e < DDIM; e++) {
            float s = sM[k][e];
            #pragma unroll
            for (int d = 0; d <= e; d++) {   // L is lower-triangular
                s = fmaf(ep[d], sL[k][e][d], s);
            }
            mix[e] = fmaf(wk, s, mix[e]);
        }
    }

    // derive per-h constants
    const float AS = ALPHA * (BASE_SCALE / (float)HIDDEN);
    float span[SPAN_D];
    span[0] = mix[0]; span[1] = mix[1];
    #pragma unroll
    for (int d = 0; d < 8; d++) span[2 + d] = mix[4 + d];

    g_n2[h] = make_float2(mix[2], mix[3]);
    g_mA[h] = make_float2(AS * mix[0], AS * mix[1]);
    #pragma unroll
    for (int d = 0; d < 8; d++) g_IA[h * 8 + d] = ALPHA * mix[4 + d];
    #pragma unroll
    for (int d = 0; d < SPAN_D; d++) g_span[h * SPAN_D + d] = span[d];

    __syncthreads();   // g_span visible to all threads in this CTA

    // ---- Gram G = span^T span (fp64): 800 threads, pair p x segment seg ----
    if (tid < 800) {
        int p = tid >> 3;          // 0..99
        int seg = tid & 7;         // 0..7 -> 128 h each
        int a = p / 10, b = p % 10;
        const float* pa = g_span + (size_t)(seg * 128) * SPAN_D;
        double s0 = 0.0, s1 = 0.0, s2 = 0.0, s3 = 0.0;
        #pragma unroll 4
        for (int i = 0; i < 128; i += 4) {
            s0 += (double)pa[(i+0)*SPAN_D + a] * (double)pa[(i+0)*SPAN_D + b];
            s1 += (double)pa[(i+1)*SPAN_D + a] * (double)pa[(i+1)*SPAN_D + b];
            s2 += (double)pa[(i+2)*SPAN_D + a] * (double)pa[(i+2)*SPAN_D + b];
            s3 += (double)pa[(i+3)*SPAN_D + a] * (double)pa[(i+3)*SPAN_D + b];
        }
        sPart[p][seg] = (s0 + s1) + (s2 + s3);
    }
    __syncthreads();
    if (tid < 100) {
        double s = 0.0;
        #pragma unroll
        for (int seg = 0; seg < 8; seg++) s += sPart[tid][seg];
        sA[tid] = s;
        sB[tid] = ((tid / 10) == (tid % 10)) ? 1.0 : 0.0;
    }

    // ---- parallel Gauss-Jordan inversion (SPD, no pivoting), 100 threads ----
    const int gi = tid / 10, gj = tid % 10;
    #pragma unroll 1
    for (int k = 0; k < SPAN_D; k++) {
        __syncthreads();
        double piv = 0.0, akj = 0.0, bkj = 0.0, f = 0.0, aij = 0.0, bij = 0.0;
        if (tid < 100) {
            piv = sA[k * 10 + k];
            akj = sA[k * 10 + gj];
            bkj = sB[k * 10 + gj];
            f   = sA[gi * 10 + k];
            aij = sA[tid];
            bij = sB[tid];
        }
        __syncthreads();
        if (tid < 100) {
            double pinv = 1.0 / piv;
            if (gi == k) {
                sA[tid] = akj * pinv;
                sB[tid] = bkj * pinv;
            } else {
                double fp = f * pinv;
                sA[tid] = aij - fp * akj;
                sB[tid] = bij - fp * bkj;
            }
        }
    }
    __syncthreads();
    if (tid < 100) sGf[tid] = (float)sB[tid];
    __syncthreads();

    // pinv[d][h] = sum_j Ginv[d][j] * span[h][j]  (store transposed [h][d], fp32)
    #pragma unroll
    for (int d = 0; d < SPAN_D; d++) {
        float s = 0.f;
        #pragma unroll
        for (int j = 0; j < SPAN_D; j++) s = fmaf(sGf[d * 10 + j], span[j], s);
        g_pinvT[h * SPAN_D + d] = s;
    }
}

// ============================ RNN kernel ============================
// One CTA per batch. 256 threads, each owns 4 consecutive hidden units.
__global__ void __launch_bounds__(256, 1) rnn_kernel(const float* __restrict__ x)
{
    __shared__ float  sx[SEQ * INPUT_SIZE];   // 16 KB: x[b] staged
    __shared__ float2 sred[2][8];             // ping-pong warp partials (p0,p1)

    const int tid  = threadIdx.x;
    const int lane = tid & 31;
    const int wid  = tid >> 5;
    const int b    = blockIdx.x;

    // stage x[b] into smem (coalesced float4)
    #pragma unroll
    for (int i = 0; i < (SEQ * INPUT_SIZE / 4) / 256; i++)
        ((float4*)sx)[i * 256 + tid] =
            ((const float4*)(x + (size_t)b * SEQ * INPUT_SIZE))[i * 256 + tid];

    // per-thread constants for h = 4*tid .. 4*tid+3
    float n0[4], n1[4], m0[4], m1[4], IA[4][8];
    #pragma unroll
    for (int i = 0; i < 4; i++) {
        int hh = 4 * tid + i;
        float2 t = g_n2[hh]; n0[i] = t.x; n1[i] = t.y;
        t = g_mA[hh];        m0[i] = t.x; m1[i] = t.y;
        float4 a4 = ((const float4*)g_IA)[hh * 2 + 0];
        float4 b4 = ((const float4*)g_IA)[hh * 2 + 1];
        IA[i][0]=a4.x; IA[i][1]=a4.y; IA[i][2]=a4.z; IA[i][3]=a4.w;
        IA[i][4]=b4.x; IA[i][5]=b4.y; IA[i][6]=b4.z; IA[i][7]=b4.w;
    }

    float h[4] = {0.f, 0.f, 0.f, 0.f};
    float* hout = g_hid + ((size_t)b << 19) + 4 * tid;   // [b][t][h]
    __syncthreads();

    int par = 0;
    #pragma unroll 1
    for (int t = 0; t < SEQ; t++) {
        // tanh(h) = 1 - 2/(exp(2h)+1)
        float th[4];
        #pragma unroll
        for (int i = 0; i < 4; i++) {
            float e = __expf(2.f * h[i]);
            th[i] = 1.f - __fdividef(2.f, e + 1.f);
        }

        float p0 = fmaf(th[0], n0[0], th[1] * n0[1]) + fmaf(th[2], n0[2], th[3] * n0[3]);
        float p1 = fmaf(th[0], n1[0], th[1] * n1[1]) + fmaf(th[2], n1[2], th[3] * n1[3]);
        #pragma unroll
        for (int o = 16; o > 0; o >>= 1) {
            p0 += __shfl_xor_sync(0xffffffffu, p0, o);
            p1 += __shfl_xor_sync(0xffffffffu, p1, o);
        }
        if (lane == 0) sred[par][wid] = make_float2(p0, p1);

        // x_t @ (alpha*I)^T  — independent of the reduction, overlaps shfl/bar
        float4 xa = ((const float4*)sx)[t * 2 + 0];
        float4 xb = ((const float4*)sx)[t * 2 + 1];
        float xi[4];
        #pragma unroll
        for (int i = 0; i < 4; i++) {
            xi[i] = xa.x*IA[i][0] + xa.y*IA[i][1] + xa.z*IA[i][2] + xa.w*IA[i][3]
                  + xb.x*IA[i][4] + xb.y*IA[i][5] + xb.z*IA[i][6] + xb.w*IA[i][7];
        }

        __syncthreads();
        // stage-2: 8 warp partials, redundant 3-level butterfly in each warp
        float2 v = sred[par][lane & 7];
        #pragma unroll
        for (int o = 4; o > 0; o >>= 1) {
            v.x += __shfl_xor_sync(0xffffffffu, v.x, o);
            v.y += __shfl_xor_sync(0xffffffffu, v.y, o);
        }

        // h_new = 0.9h + q0*mA0 + q1*mA1 + xi  (scales prefolded)
        #pragma unroll
        for (int i = 0; i < 4; i++)
            h[i] = fmaf(0.9f, h[i], fmaf(v.x, m0[i], fmaf(v.y, m1[i], xi[i])));

        *(float4*)(hout + ((size_t)t << 10)) = make_float4(h[0], h[1], h[2], h[3]);
        par ^= 1;
    }
}

// ============================ projection kernel ============================
// out[b,t,d] = sum_h pinv[d][h] * hid[b,t,h]; thread per (b,t).
__global__ void __launch_bounds__(256) proj_kernel(float* __restrict__ out)
{
    extern __shared__ float spv[];   // [1024][12] padded pinv rows, 48 KB
    const int tid = threadIdx.x;
    for (int i = tid; i < HIDDEN * 12; i += 256) {
        int hh = i / 12, d = i % 12;
        spv[i] = (d < SPAN_D) ? g_pinvT[hh * SPAN_D + d] : 0.f;
    }
    __syncthreads();

    const int bt = blockIdx.x * 256 + tid;          // 0..32767
    const float4* hp = (const float4*)(g_hid + (size_t)bt * HIDDEN);

    float acc[SPAN_D];
    #pragma unroll
    for (int d = 0; d < SPAN_D; d++) acc[d] = 0.f;

    #pragma unroll 4
    for (int j = 0; j < HIDDEN / 4; j++) {
        float4 hv = hp[j];
        const float* base = &spv[(j * 4) * 12];
        {
            const float4* pv = (const float4*)(base + 0);
            float4 a = pv[0], bq = pv[1], c = pv[2];
            acc[0] += hv.x*a.x;  acc[1] += hv.x*a.y;  acc[2] += hv.x*a.z;  acc[3] += hv.x*a.w;
            acc[4] += hv.x*bq.x; acc[5] += hv.x*bq.y; acc[6] += hv.x*bq.z; acc[7] += hv.x*bq.w;
            acc[8] += hv.x*c.x;  acc[9] += hv.x*c.y;
        }
        {
            const float4* pv = (const float4*)(base + 12);
            float4 a = pv[0], bq = pv[1], c = pv[2];
            acc[0] += hv.y*a.x;  acc[1] += hv.y*a.y;  acc[2] += hv.y*a.z;  acc[3] += hv.y*a.w;
            acc[4] += hv.y*bq.x; acc[5] += hv.y*bq.y; acc[6] += hv.y*bq.z; acc[7] += hv.y*bq.w;
            acc[8] += hv.y*c.x;  acc[9] += hv.y*c.y;
        }
        {
            const float4* pv = (const float4*)(base + 24);
            float4 a = pv[0], bq = pv[1], c = pv[2];
            acc[0] += hv.z*a.x;  acc[1] += hv.z*a.y;  acc[2] += hv.z*a.z;  acc[3] += hv.z*a.w;
            acc[4] += hv.z*bq.x; acc[5] += hv.z*bq.y; acc[6] += hv.z*bq.z; acc[7] += hv.z*bq.w;
            acc[8] += hv.z*c.x;  acc[9] += hv.z*c.y;
        }
        {
            const float4* pv = (const float4*)(base + 36);
            float4 a = pv[0], bq = pv[1], c = pv[2];
            acc[0] += hv.w*a.x;  acc[1] += hv.w*a.y;  acc[2] += hv.w*a.z;  acc[3] += hv.w*a.w;
            acc[4] += hv.w*bq.x; acc[5] += hv.w*bq.y; acc[6] += hv.w*bq.z; acc[7] += hv.w*bq.w;
            acc[8] += hv.w*c.x;  acc[9] += hv.w*c.y;
        }
    }

    float* op = out + (size_t)bt * SPAN_D;
    #pragma unroll
    for (int d = 0; d < SPAN_D; d++) op[d] = acc[d];
}

// ============================ launcher ============================
extern "C" void kernel_launch(void* const* d_in, const int* in_sizes, int n_in,
                              void* d_out, int out_size)
{
    const float* x     = (const float*)d_in[0];   // (64,512,8)
    const float* eps   = (const float*)d_in[1];   // (4,1024,12)
    const float* means = (const float*)d_in[2];   // (4,12)
    const float* stril = (const float*)d_in[3];   // (4,12,12)
    const float* mw    = (const float*)d_in[4];   // (4,)
    float* out = (float*)d_out;                   // (64,512,10)

    static bool attr_set = false;
    if (!attr_set) {
        cudaFuncSetAttribute(proj_kernel,
                             cudaFuncAttributeMaxDynamicSharedMemorySize,
                             HIDDEN * 12 * sizeof(float));
        attr_set = true;
    }

    setup_kernel<<<1, 1024>>>(eps, means, stril, mw);
    rnn_kernel<<<BATCH, 256>>>(x);
    proj_kernel<<<(BATCH * SEQ) / 256, 256, HIDDEN * 12 * sizeof(float)>>>(out);
}

// round 7
// speedup vs baseline: 2.8792x; 1.3653x over previous
#include <cuda_runtime.h>
#include <cuda_bf16.h>
#include <cstdint>

// Problem constants
#define RANK 2
#define INPUT_SIZE 8
#define HIDDEN 1024
#define NMIX 4
#define ALPHA 0.1f
#define BASE_SCALE 500.0f
#define DDIM 12              // 2*RANK + INPUT_SIZE
#define BATCH 64
#define SEQ 512
#define SPAN_D 10            // RANK + INPUT_SIZE

// ---------------- scratch (device globals: allocation-free) ----------------
__device__ float2 g_n2[HIDDEN];            // (n0, n1) per hidden unit
__device__ float2 g_mA[HIDDEN];            // alpha*s*(m0, m1)
__device__ float  g_IA[HIDDEN * 8];        // alpha*I  [h][8]
__device__ float  g_span[HIDDEN * SPAN_D]; // span matrix scratch [h][d]
__device__ float  g_pinvT[HIDDEN * SPAN_D];// pinv transposed: [h][d]
__device__ float  g_hid[(size_t)BATCH * SEQ * HIDDEN]; // 128 MB hiddens

// HW tanh approximation: single MUFU op (sm_75+)
__device__ __forceinline__ float tanh_hw(float x) {
    float r;
    asm("tanh.approx.f32 %0, %1;" : "=f"(r) : "f"(x));
    return r;
}

// ============================ setup kernel ============================
__global__ void __launch_bounds__(1024) setup_kernel(
    const float* __restrict__ eps,     // (4,1024,12)
    const float* __restrict__ means,   // (4,12)
    const float* __restrict__ stril,   // (4,12,12)
    const float* __restrict__ mw)      // (4,)
{
    __shared__ float  sL[NMIX][DDIM][DDIM];
    __shared__ float  sM[NMIX][DDIM];
    __shared__ float  sw[NMIX];
    __shared__ float  sPart[100][8];   // Gram partials: pair x segment (fp32)
    __shared__ double sA[100];         // GJ workspace (fp64, tiny op count)
    __shared__ double sB[100];         // GJ inverse accumulator
    __shared__ float  sGf[100];        // Ginv in fp32

    const int tid = threadIdx.x;

    // L = tril(raw,-1) + (|diag-1e-12|+1e-12) * I
    if (tid < NMIX * DDIM * DDIM) {
        int r = (tid / DDIM) % DDIM;
        int c = tid % DDIM;
        float raw = stril[tid];
        float v;
        if (r > c)      v = raw;
        else if (r == c) v = fabsf(raw - 1e-12f) + 1e-12f;
        else            v = 0.f;
        sL[tid / (DDIM * DDIM)][r][c] = v;
    }
    if (tid < NMIX * DDIM) sM[tid / DDIM][tid % DDIM] = means[tid];
    if (tid == 0) {
        float t4[NMIX]; float s = 0.f;
        #pragma unroll
        for (int k = 0; k < NMIX; k++) { t4[k] = fmaxf(mw[k], 1e-6f); s += t4[k]; }
        #pragma unroll
        for (int k = 0; k < NMIX; k++) sw[k] = t4[k] / s;
    }
    __syncthreads();

    // mixed[h][e] = sum_k w_k * (means[k][e] + sum_{d<=e} eps[k,h,d]*L[k,e,d])
    const int h = tid;
    float mix[DDIM];
    #pragma unroll
    for (int e = 0; e < DDIM; e++) mix[e] = 0.f;

    #pragma unroll
    for (int k = 0; k < NMIX; k++) {
        float wk = sw[k];
        const float4* p = (const float4*)(eps + ((size_t)k * HIDDEN + h) * DDIM);
        float4 a = p[0], b = p[1], c = p[2];
        float ep[DDIM] = {a.x,a.y,a.z,a.w, b.x,b.y,b.z,b.w, c.x,c.y,c.z,c.w};
        #pragma unroll
        for (int e = 0; e < DDIM; e++) {
            float s = sM[k][e];
            #pragma unroll
            for (int d = 0; d <= e; d++) {   // L is lower-triangular
                s = fmaf(ep[d], sL[k][e][d], s);
            }
            mix[e] = fmaf(wk, s, mix[e]);
        }
    }

    // derive per-h constants
    const float AS = ALPHA * (BASE_SCALE / (float)HIDDEN);
    float span[SPAN_D];
    span[0] = mix[0]; span[1] = mix[1];
    #pragma unroll
    for (int d = 0; d < 8; d++) span[2 + d] = mix[4 + d];

    g_n2[h] = make_float2(mix[2], mix[3]);
    g_mA[h] = make_float2(AS * mix[0], AS * mix[1]);
    #pragma unroll
    for (int d = 0; d < 8; d++) g_IA[h * 8 + d] = ALPHA * mix[4 + d];
    #pragma unroll
    for (int d = 0; d < SPAN_D; d++) g_span[h * SPAN_D + d] = span[d];

    __syncthreads();   // g_span visible to all threads in this CTA

    // ---- Gram G = span^T span: fp32 partials (NO fp64 pipe in the hot loop) ----
    if (tid < 800) {
        int p = tid >> 3;          // 0..99
        int seg = tid & 7;         // 0..7 -> 128 h each
        int a = p / 10, b = p % 10;
        const float* pa = g_span + (size_t)(seg * 128) * SPAN_D;
        float s0 = 0.f, s1 = 0.f, s2 = 0.f, s3 = 0.f;
        #pragma unroll 4
        for (int i = 0; i < 128; i += 4) {
            s0 = fmaf(pa[(i+0)*SPAN_D + a], pa[(i+0)*SPAN_D + b], s0);
            s1 = fmaf(pa[(i+1)*SPAN_D + a], pa[(i+1)*SPAN_D + b], s1);
            s2 = fmaf(pa[(i+2)*SPAN_D + a], pa[(i+2)*SPAN_D + b], s2);
            s3 = fmaf(pa[(i+3)*SPAN_D + a], pa[(i+3)*SPAN_D + b], s3);
        }
        sPart[p][seg] = (s0 + s1) + (s2 + s3);
    }
    __syncthreads();
    if (tid < 100) {
        double s = 0.0;
        #pragma unroll
        for (int seg = 0; seg < 8; seg++) s += (double)sPart[tid][seg];
        sA[tid] = s;
        sB[tid] = ((tid / 10) == (tid % 10)) ? 1.0 : 0.0;
    }

    // ---- parallel Gauss-Jordan inversion (SPD, no pivoting), 100 threads, fp64 ----
    const int gi = tid / 10, gj = tid % 10;
    #pragma unroll 1
    for (int k = 0; k < SPAN_D; k++) {
        __syncthreads();
        double piv = 0.0, akj = 0.0, bkj = 0.0, f = 0.0, aij = 0.0, bij = 0.0;
        if (tid < 100) {
            piv = sA[k * 10 + k];
            akj = sA[k * 10 + gj];
            bkj = sB[k * 10 + gj];
            f   = sA[gi * 10 + k];
            aij = sA[tid];
            bij = sB[tid];
        }
        __syncthreads();
        if (tid < 100) {
            double pinv = 1.0 / piv;
            if (gi == k) {
                sA[tid] = akj * pinv;
                sB[tid] = bkj * pinv;
            } else {
                double fp = f * pinv;
                sA[tid] = aij - fp * akj;
                sB[tid] = bij - fp * bkj;
            }
        }
    }
    __syncthreads();
    if (tid < 100) sGf[tid] = (float)sB[tid];
    __syncthreads();

    // pinv[d][h] = sum_j Ginv[d][j] * span[h][j]  (store transposed [h][d], fp32)
    #pragma unroll
    for (int d = 0; d < SPAN_D; d++) {
        float s = 0.f;
        #pragma unroll
        for (int j = 0; j < SPAN_D; j++) s = fmaf(sGf[d * 10 + j], span[j], s);
        g_pinvT[h * SPAN_D + d] = s;
    }
}

// ============================ RNN kernel ============================
// One CTA per batch. 256 threads, each owns 4 consecutive hidden units.
__global__ void __launch_bounds__(256, 1) rnn_kernel(const float* __restrict__ x)
{
    __shared__ float  sx[SEQ * INPUT_SIZE];   // 16 KB: x[b] staged
    __shared__ float4 sred[2][4];             // ping-pong: 8 x float2(p0,p1) as 4 x float4

    const int tid  = threadIdx.x;
    const int lane = tid & 31;
    const int wid  = tid >> 5;
    const int b    = blockIdx.x;

    // stage x[b] into smem (coalesced float4)
    #pragma unroll
    for (int i = 0; i < (SEQ * INPUT_SIZE / 4) / 256; i++)
        ((float4*)sx)[i * 256 + tid] =
            ((const float4*)(x + (size_t)b * SEQ * INPUT_SIZE))[i * 256 + tid];

    // per-thread constants for h = 4*tid .. 4*tid+3
    float n0[4], n1[4], m0[4], m1[4], IA[4][8];
    #pragma unroll
    for (int i = 0; i < 4; i++) {
        int hh = 4 * tid + i;
        float2 t = g_n2[hh]; n0[i] = t.x; n1[i] = t.y;
        t = g_mA[hh];        m0[i] = t.x; m1[i] = t.y;
        float4 a4 = ((const float4*)g_IA)[hh * 2 + 0];
        float4 b4 = ((const float4*)g_IA)[hh * 2 + 1];
        IA[i][0]=a4.x; IA[i][1]=a4.y; IA[i][2]=a4.z; IA[i][3]=a4.w;
        IA[i][4]=b4.x; IA[i][5]=b4.y; IA[i][6]=b4.z; IA[i][7]=b4.w;
    }

    float h[4] = {0.f, 0.f, 0.f, 0.f};
    float* hout = g_hid + ((size_t)b << 19) + 4 * tid;   // [b][t][h]
    __syncthreads();

    int par = 0;
    #pragma unroll 1
    for (int t = 0; t < SEQ; t++) {
        // tanh via single MUFU op
        float th[4];
        #pragma unroll
        for (int i = 0; i < 4; i++) th[i] = tanh_hw(h[i]);

        // per-thread 4-way product tree, then 5-level interleaved dual butterfly
        float p0 = fmaf(th[0], n0[0], th[1] * n0[1]) + fmaf(th[2], n0[2], th[3] * n0[3]);
        float p1 = fmaf(th[0], n1[0], th[1] * n1[1]) + fmaf(th[2], n1[2], th[3] * n1[3]);
        #pragma unroll
        for (int o = 16; o > 0; o >>= 1) {
            p0 += __shfl_xor_sync(0xffffffffu, p0, o);
            p1 += __shfl_xor_sync(0xffffffffu, p1, o);
        }
        if (lane == 0) ((float2*)&sred[par][0])[wid] = make_float2(p0, p1);

        // x_t @ (alpha*I)^T  — independent of the reduction, overlaps shfl/bar
        float4 xa = ((const float4*)sx)[t * 2 + 0];
        float4 xb = ((const float4*)sx)[t * 2 + 1];
        float xi[4];
        #pragma unroll
        for (int i = 0; i < 4; i++) {
            xi[i] = xa.x*IA[i][0] + xa.y*IA[i][1] + xa.z*IA[i][2] + xa.w*IA[i][3]
                  + xb.x*IA[i][4] + xb.y*IA[i][5] + xb.z*IA[i][6] + xb.w*IA[i][7];
        }

        __syncthreads();
        // stage-2: 4 broadcast LDS.128 + depth-3 FADD tree (no shfl chain)
        float4 r0 = sred[par][0];
        float4 r1 = sred[par][1];
        float4 r2 = sred[par][2];
        float4 r3 = sred[par][3];
        float q0 = ((r0.x + r0.z) + (r1.x + r1.z)) + ((r2.x + r2.z) + (r3.x + r3.z));
        float q1 = ((r0.y + r0.w) + (r1.y + r1.w)) + ((r2.y + r2.w) + (r3.y + r3.w));

        // h_new = 0.9h + q0*mA0 + q1*mA1 + xi  (scales prefolded)
        #pragma unroll
        for (int i = 0; i < 4; i++)
            h[i] = fmaf(0.9f, h[i], fmaf(q0, m0[i], fmaf(q1, m1[i], xi[i])));

        *(float4*)(hout + ((size_t)t << 10)) = make_float4(h[0], h[1], h[2], h[3]);
        par ^= 1;
    }
}

// ============================ projection kernel ============================
// out[b,t,d] = sum_h pinv[d][h] * hid[b,t,h]; thread per (b,t).
__global__ void __launch_bounds__(256) proj_kernel(float* __restrict__ out)
{
    extern __shared__ float spv[];   // [1024][12] padded pinv rows, 48 KB
    const int tid = threadIdx.x;
    for (int i = tid; i < HIDDEN * 12; i += 256) {
        int hh = i / 12, d = i % 12;
        spv[i] = (d < SPAN_D) ? g_pinvT[hh * SPAN_D + d] : 0.f;
    }
    __syncthreads();

    const int bt = blockIdx.x * 256 + tid;          // 0..32767
    const float4* hp = (const float4*)(g_hid + (size_t)bt * HIDDEN);

    float acc[SPAN_D];
    #pragma unroll
    for (int d = 0; d < SPAN_D; d++) acc[d] = 0.f;

    #pragma unroll 4
    for (int j = 0; j < HIDDEN / 4; j++) {
        float4 hv = hp[j];
        const float* base = &spv[(j * 4) * 12];
        {
            const float4* pv = (const float4*)(base + 0);
            float4 a = pv[0], bq = pv[1], c = pv[2];
            acc[0] += hv.x*a.x;  acc[1] += hv.x*a.y;  acc[2] += hv.x*a.z;  acc[3] += hv.x*a.w;
            acc[4] += hv.x*bq.x; acc[5] += hv.x*bq.y; acc[6] += hv.x*bq.z; acc[7] += hv.x*bq.w;
            acc[8] += hv.x*c.x;  acc[9] += hv.x*c.y;
        }
        {
            const float4* pv = (const float4*)(base + 12);
            float4 a = pv[0], bq = pv[1], c = pv[2];
            acc[0] += hv.y*a.x;  acc[1] += hv.y*a.y;  acc[2] += hv.y*a.z;  acc[3] += hv.y*a.w;
            acc[4] += hv.y*bq.x; acc[5] += hv.y*bq.y; acc[6] += hv.y*bq.z; acc[7] += hv.y*bq.w;
            acc[8] += hv.y*c.x;  acc[9] += hv.y*c.y;
        }
        {
            const float4* pv = (const float4*)(base + 24);
            float4 a = pv[0], bq = pv[1], c = pv[2];
            acc[0] += hv.z*a.x;  acc[1] += hv.z*a.y;  acc[2] += hv.z*a.z;  acc[3] += hv.z*a.w;
            acc[4] += hv.z*bq.x; acc[5] += hv.z*bq.y; acc[6] += hv.z*bq.z; acc[7] += hv.z*bq.w;
            acc[8] += hv.z*c.x;  acc[9] += hv.z*c.y;
        }
        {
            const float4* pv = (const float4*)(base + 36);
            float4 a = pv[0], bq = pv[1], c = pv[2];
            acc[0] += hv.w*a.x;  acc[1] += hv.w*a.y;  acc[2] += hv.w*a.z;  acc[3] += hv.w*a.w;
            acc[4] += hv.w*bq.x; acc[5] += hv.w*bq.y; acc[6] += hv.w*bq.z; acc[7] += hv.w*bq.w;
            acc[8] += hv.w*c.x;  acc[9] += hv.w*c.y;
        }
    }

    float* op = out + (size_t)bt * SPAN_D;
    #pragma unroll
    for (int d = 0; d < SPAN_D; d++) op[d] = acc[d];
}

// ============================ launcher ============================
extern "C" void kernel_launch(void* const* d_in, const int* in_sizes, int n_in,
                              void* d_out, int out_size)
{
    const float* x     = (const float*)d_in[0];   // (64,512,8)
    const float* eps   = (const float*)d_in[1];   // (4,1024,12)
    const float* means = (const float*)d_in[2];   // (4,12)
    const float* stril = (const float*)d_in[3];   // (4,12,12)
    const float* mw    = (const float*)d_in[4];   // (4,)
    float* out = (float*)d_out;                   // (64,512,10)

    static bool attr_set = false;
    if (!attr_set) {
        cudaFuncSetAttribute(proj_kernel,
                             cudaFuncAttributeMaxDynamicSharedMemorySize,
                             HIDDEN * 12 * sizeof(float));
        attr_set = true;
    }

    setup_kernel<<<1, 1024>>>(eps, means, stril, mw);
    rnn_kernel<<<BATCH, 256>>>(x);
    proj_kernel<<<(BATCH * SEQ) / 256, 256, HIDDEN * 12 * sizeof(float)>>>(out);
}